// round 11
// baseline (speedup 1.0000x reference)
#include <cuda_runtime.h>
#include <cuda_bf16.h>
#include <math.h>

// Problem constants (fixed by reference setup_inputs)
#define BD     8
#define LD     1024
#define SD     1000
#define DMODEL 1024
#define DLLM   4096
#define NH     8
#define EDIM   128
#define INNER  1024   // NH*EDIM

#define ATTN_SCALE 0.088388347648318447f  // 1/sqrt(128)

typedef unsigned long long ull;
typedef unsigned int u32;

// Scratch (device globals: no allocation allowed)
__device__ float g_Q[(size_t)BD * LD * INNER];    // (B*L, INNER)
__device__ float g_K[(size_t)SD * INNER];         // (S, INNER)
__device__ float g_V[(size_t)SD * INNER];         // (S, INNER)
__device__ float g_ctx[(size_t)BD * LD * INNER];  // (B*L, INNER)

// ---- packed f32x2 helpers (attention kernel) -------------------------------
__device__ __forceinline__ ull pack2(float x, float y) {
    ull r; asm("mov.b64 %0, {%1,%2};" : "=l"(r) : "f"(x), "f"(y)); return r;
}
__device__ __forceinline__ float2 unpack2(ull v) {
    float2 r; asm("mov.b64 {%0,%1}, %2;" : "=f"(r.x), "=f"(r.y) : "l"(v)); return r;
}
__device__ __forceinline__ void fma2(ull& c, ull a, ull b) {
    asm("fma.rn.f32x2 %0, %1, %2, %0;" : "+l"(c) : "l"(a), "l"(b));
}
__device__ __forceinline__ ull mul2(ull a, ull b) {
    ull r; asm("mul.rn.f32x2 %0, %1, %2;" : "=l"(r) : "l"(a), "l"(b)); return r;
}

// ============================================================================
// Split-bf16 3-pass tensor-core GEMM: C = A@W + bias (fp32 in/out).
// a = ah + al (bf16), b = bh + bl; D += ah*bh + ah*bl + al*bh.
// Dropped al*bl term is ~2^-16 relative -> rel_err ~1e-5 << 1e-3.
// CTA: 128x128 tile, BK=16, 256 threads (8 warps, each 32m x 64n).
// Smem tiles: Ah/Al [128][24] (row-major k), Bh/Bl [128][24] (n-major!, so a
// B fragment b32 load grabs (k,k+1) for one n). Stride 24 bf16 = 48B makes
// fragment LDS bank-conflict-free ({12*gid + tig} mod 32 is a permutation).
// ============================================================================
#define TSTRIDE 24
#define TILE_E  (128 * TSTRIDE)            // 3072 bf16 per array
#define GEMM_SMEM_BYTES (8 * TILE_E * 2)   // 4 arrays x 2 buffers x 2B = 49152

__device__ __forceinline__ void mma_bf16(float* d, const u32* a, u32 b0, u32 b1) {
    asm volatile(
        "mma.sync.aligned.m16n8k16.row.col.f32.bf16.bf16.f32 "
        "{%0,%1,%2,%3}, {%4,%5,%6,%7}, {%8,%9}, {%0,%1,%2,%3};\n"
        : "+f"(d[0]), "+f"(d[1]), "+f"(d[2]), "+f"(d[3])
        : "r"(a[0]), "r"(a[1]), "r"(a[2]), "r"(a[3]), "r"(b0), "r"(b1));
}

// Split 8 consecutive floats into hi/lo bf16 and store as two STS.128.
__device__ __forceinline__ void split8_sts(const float* v,
                                           __nv_bfloat16* Hdst,
                                           __nv_bfloat16* Ldst) {
    u32 h[4], l[4];
    #pragma unroll
    for (int i = 0; i < 4; i++) {
        float x = v[2 * i], y = v[2 * i + 1];
        __nv_bfloat162 hh = __floats2bfloat162_rn(x, y);
        float rx = x - __bfloat162float(hh.x);
        float ry = y - __bfloat162float(hh.y);
        __nv_bfloat162 ll = __floats2bfloat162_rn(rx, ry);
        h[i] = *(u32*)&hh;
        l[i] = *(u32*)&ll;
    }
    *(uint4*)Hdst = make_uint4(h[0], h[1], h[2], h[3]);
    *(uint4*)Ldst = make_uint4(l[0], l[1], l[2], l[3]);
}

__device__ __forceinline__ void gemm3_body(
    const float* __restrict__ A, const float* __restrict__ W,
    const float* __restrict__ bias, float* __restrict__ C,
    int M, int N, int K, int row0, int col0)
{
    extern __shared__ __nv_bfloat16 sb[];

    const int tid  = threadIdx.x;
    const int lane = tid & 31;
    const int warp = tid >> 5;
    const int gid  = lane >> 2;   // 0..7
    const int tig  = lane & 3;    // 0..3
    const int m0   = (warp & 3) * 32;   // warp m origin in tile
    const int n0   = (warp >> 2) * 64;  // warp n origin in tile

    // loader mapping: 256 threads, lr = row (A) / n (B), lk = k base (0 or 8)
    const int lr = tid & 127;
    const int lk = (tid >> 7) * 8;

    float acc[2][8][4];
    #pragma unroll
    for (int mt = 0; mt < 2; mt++)
        #pragma unroll
        for (int j = 0; j < 8; j++)
            #pragma unroll
            for (int q = 0; q < 4; q++) acc[mt][j][q] = 0.f;

    const bool arow_ok = (row0 + lr) < M;
    const float* Apt = A + (size_t)(row0 + lr) * K + lk;      // A[row][lk+..]
    const float* Wpt = W + (size_t)lk * N + (col0 + lr);      // W[lk+i][col0+lr]

    float av[8];   // A prefetch (8 consecutive k)
    float bv[8];   // B prefetch (8 consecutive k, one n) -- transposed store

    // ---- prefetch tile 0 ----
    {
        float4 t0 = make_float4(0.f, 0.f, 0.f, 0.f), t1 = t0;
        if (arow_ok) { t0 = *(const float4*)(Apt); t1 = *(const float4*)(Apt + 4); }
        av[0]=t0.x; av[1]=t0.y; av[2]=t0.z; av[3]=t0.w;
        av[4]=t1.x; av[5]=t1.y; av[6]=t1.z; av[7]=t1.w;
        #pragma unroll
        for (int i = 0; i < 8; i++) bv[i] = Wpt[(size_t)i * N];
    }
    // ---- store tile 0 into buffer 0 ----
    {
        __nv_bfloat16* Ah = sb;                 __nv_bfloat16* Al = Ah + TILE_E;
        __nv_bfloat16* Bh = Al + TILE_E;        __nv_bfloat16* Bl = Bh + TILE_E;
        split8_sts(av, &Ah[lr * TSTRIDE + lk], &Al[lr * TSTRIDE + lk]);
        split8_sts(bv, &Bh[lr * TSTRIDE + lk], &Bl[lr * TSTRIDE + lk]);
    }
    __syncthreads();

    int cur = 0;
    for (int k0 = 16; k0 <= K; k0 += 16) {
        const bool more = (k0 < K);
        if (more) {
            float4 t0 = make_float4(0.f, 0.f, 0.f, 0.f), t1 = t0;
            if (arow_ok) { t0 = *(const float4*)(Apt + k0); t1 = *(const float4*)(Apt + k0 + 4); }
            av[0]=t0.x; av[1]=t0.y; av[2]=t0.z; av[3]=t0.w;
            av[4]=t1.x; av[5]=t1.y; av[6]=t1.z; av[7]=t1.w;
            #pragma unroll
            for (int i = 0; i < 8; i++) bv[i] = Wpt[(size_t)(k0 + i) * N];
        }

        // ---- compute on current buffer ----
        const __nv_bfloat16* Ah = sb + (size_t)cur * 4 * TILE_E;
        const __nv_bfloat16* Al = Ah + TILE_E;
        const __nv_bfloat16* Bh = Al + TILE_E;
        const __nv_bfloat16* Bl = Bh + TILE_E;

        u32 ah[2][4], al[2][4];
        #pragma unroll
        for (int mt = 0; mt < 2; mt++) {
            int r = m0 + mt * 16 + gid;
            ah[mt][0] = *(const u32*)&Ah[(r    ) * TSTRIDE + tig * 2    ];
            ah[mt][1] = *(const u32*)&Ah[(r + 8) * TSTRIDE + tig * 2    ];
            ah[mt][2] = *(const u32*)&Ah[(r    ) * TSTRIDE + tig * 2 + 8];
            ah[mt][3] = *(const u32*)&Ah[(r + 8) * TSTRIDE + tig * 2 + 8];
            al[mt][0] = *(const u32*)&Al[(r    ) * TSTRIDE + tig * 2    ];
            al[mt][1] = *(const u32*)&Al[(r + 8) * TSTRIDE + tig * 2    ];
            al[mt][2] = *(const u32*)&Al[(r    ) * TSTRIDE + tig * 2 + 8];
            al[mt][3] = *(const u32*)&Al[(r + 8) * TSTRIDE + tig * 2 + 8];
        }
        #pragma unroll
        for (int j = 0; j < 8; j++) {
            int n = n0 + j * 8 + gid;
            u32 bh0 = *(const u32*)&Bh[n * TSTRIDE + tig * 2    ];
            u32 bh1 = *(const u32*)&Bh[n * TSTRIDE + tig * 2 + 8];
            u32 bl0 = *(const u32*)&Bl[n * TSTRIDE + tig * 2    ];
            u32 bl1 = *(const u32*)&Bl[n * TSTRIDE + tig * 2 + 8];
            #pragma unroll
            for (int mt = 0; mt < 2; mt++) {
                mma_bf16(acc[mt][j], ah[mt], bh0, bh1);
                mma_bf16(acc[mt][j], ah[mt], bl0, bl1);
                mma_bf16(acc[mt][j], al[mt], bh0, bh1);
            }
        }

        if (more) {
            int nxt = cur ^ 1;
            __nv_bfloat16* AhN = sb + (size_t)nxt * 4 * TILE_E;
            __nv_bfloat16* AlN = AhN + TILE_E;
            __nv_bfloat16* BhN = AlN + TILE_E;
            __nv_bfloat16* BlN = BhN + TILE_E;
            split8_sts(av, &AhN[lr * TSTRIDE + lk], &AlN[lr * TSTRIDE + lk]);
            split8_sts(bv, &BhN[lr * TSTRIDE + lk], &BlN[lr * TSTRIDE + lk]);
            __syncthreads();
            cur = nxt;
        }
    }

    // ---- epilogue: add bias, store fp32 ----
    #pragma unroll
    for (int j = 0; j < 8; j++) {
        int col = col0 + n0 + j * 8 + tig * 2;
        float2 bb = *(const float2*)(bias + col);
        #pragma unroll
        for (int mt = 0; mt < 2; mt++) {
            int r = row0 + m0 + mt * 16 + gid;
            if (r < M) {
                float2 o = make_float2(acc[mt][j][0] + bb.x, acc[mt][j][1] + bb.y);
                *(float2*)(C + (size_t)r * N + col) = o;
            }
            if (r + 8 < M) {
                float2 o = make_float2(acc[mt][j][2] + bb.x, acc[mt][j][3] + bb.y);
                *(float2*)(C + (size_t)(r + 8) * N + col) = o;
            }
        }
    }
}

// Big output projection.
__global__ __launch_bounds__(256, 2) void sgemm3(
    const float* __restrict__ A, const float* __restrict__ W,
    const float* __restrict__ bias, float* __restrict__ C,
    int M, int N, int K)
{
    gemm3_body(A, W, bias, C, M, N, K, blockIdx.y * 128, blockIdx.x * 128);
}

// Fused Q+K+V projection: grid (8, 80), no empty CTAs.
__global__ __launch_bounds__(256, 2) void proj_qkv(
    const float* __restrict__ te,
    const float* __restrict__ se, const float* __restrict__ ve,
    const float* __restrict__ Wq, const float* __restrict__ bq,
    const float* __restrict__ Wk, const float* __restrict__ bk,
    const float* __restrict__ Wv, const float* __restrict__ bv,
    float* __restrict__ Qp, float* __restrict__ Kp, float* __restrict__ Vp)
{
    const int y = blockIdx.y;
    const float *A, *W, *bia;
    float* C;
    int M, K, row0;
    if (y < 64) {
        A = te; W = Wq; bia = bq; C = Qp;
        M = BD * LD; K = DMODEL; row0 = y * 128;
    } else if (y < 72) {
        A = se; W = Wk; bia = bk; C = Kp;
        M = SD; K = DLLM; row0 = (y - 64) * 128;
    } else {
        A = ve; W = Wv; bia = bv; C = Vp;
        M = SD; K = DLLM; row0 = (y - 72) * 128;
    }
    gemm3_body(A, W, bia, C, M, INNER, K, row0, blockIdx.x * 128);
}

// ---- Flash attention (fp32, online softmax) -- unchanged passing version ---
#define AQ_STRIDE 132
#define KT_STRIDE 66
#define PS_STRIDE 66
#define KV_FLOATS 8448  // max(128*KT_STRIDE=8448, 64*128=8192)
#define ATTN_SMEM ((64 * AQ_STRIDE + KV_FLOATS + 64 * PS_STRIDE) * 4)

__global__ __launch_bounds__(256, 2) void attn_kernel()
{
    extern __shared__ float sm[];
    float* Qs = sm;                         // [64][AQ_STRIDE]
    float* KV = sm + 64 * AQ_STRIDE;        // K^T [128][KT_STRIDE] or V [64][128]
    float* Ps = KV + KV_FLOATS;             // [64][PS_STRIDE]

    const int tid = threadIdx.x;
    const int l0  = blockIdx.x * 64;
    const int h   = blockIdx.y;
    const int b   = blockIdx.z;

    const float* Qg = g_Q + ((size_t)(b * LD + l0)) * INNER + h * EDIM;
    #pragma unroll
    for (int i = 0; i < 8; i++) {
        int f = tid + i * 256;
        int r = f >> 5;
        int c = (f & 31) * 4;
        float4 v = *(const float4*)(Qg + (size_t)r * INNER + c);
        Qs[r * AQ_STRIDE + c + 0] = v.x;
        Qs[r * AQ_STRIDE + c + 1] = v.y;
        Qs[r * AQ_STRIDE + c + 2] = v.z;
        Qs[r * AQ_STRIDE + c + 3] = v.w;
    }

    const int rowb  = (tid >> 4) * 4;
    const int colb  = (tid & 15) * 4;
    const int colb2 = (tid & 15) * 8;

    float m[4], lsum[4];
    ull o2[4][4];
    #pragma unroll
    for (int i = 0; i < 4; i++) {
        m[i] = -INFINITY;
        lsum[i] = 0.f;
        #pragma unroll
        for (int j = 0; j < 4; j++) o2[i][j] = 0ull;
    }
    __syncthreads();

    for (int s0 = 0; s0 < SD; s0 += 64) {
        const float* Kg = g_K + (size_t)s0 * INNER + h * EDIM;
        #pragma unroll
        for (int i = 0; i < 8; i++) {
            int f  = tid + i * 256;
            int sr = f >> 5;
            int c  = (f & 31) * 4;
            float4 v = make_float4(0.f, 0.f, 0.f, 0.f);
            if (s0 + sr < SD) v = *(const float4*)(Kg + (size_t)sr * INNER + c);
            KV[(c + 0) * KT_STRIDE + sr] = v.x;
            KV[(c + 1) * KT_STRIDE + sr] = v.y;
            KV[(c + 2) * KT_STRIDE + sr] = v.z;
            KV[(c + 3) * KT_STRIDE + sr] = v.w;
        }
        __syncthreads();

        ull pc2[4][2];
        #pragma unroll
        for (int i = 0; i < 4; i++) { pc2[i][0] = 0ull; pc2[i][1] = 0ull; }
        #pragma unroll 4
        for (int e = 0; e < EDIM; e++) {
            ull b0 = *(const ull*)&KV[e * KT_STRIDE + colb];
            ull b1 = *(const ull*)&KV[e * KT_STRIDE + colb + 2];
            #pragma unroll
            for (int i = 0; i < 4; i++) {
                float a = Qs[(rowb + i) * AQ_STRIDE + e];
                ull a2 = pack2(a, a);
                fma2(pc2[i][0], a2, b0);
                fma2(pc2[i][1], a2, b1);
            }
        }

        #pragma unroll
        for (int i = 0; i < 4; i++) {
            float2 q0 = unpack2(pc2[i][0]);
            float2 q1 = unpack2(pc2[i][1]);
            float sc[4] = {q0.x, q0.y, q1.x, q1.y};
            #pragma unroll
            for (int j = 0; j < 4; j++) {
                sc[j] *= ATTN_SCALE;
                if (s0 + colb + j >= SD) sc[j] = -INFINITY;
            }
            float mx = fmaxf(fmaxf(sc[0], sc[1]), fmaxf(sc[2], sc[3]));
            mx = fmaxf(mx, __shfl_xor_sync(0xffffffffu, mx, 8));
            mx = fmaxf(mx, __shfl_xor_sync(0xffffffffu, mx, 4));
            mx = fmaxf(mx, __shfl_xor_sync(0xffffffffu, mx, 2));
            mx = fmaxf(mx, __shfl_xor_sync(0xffffffffu, mx, 1));
            float mn = fmaxf(m[i], mx);
            float al = __expf(m[i] - mn);
            m[i] = mn;
            float rs = 0.f;
            #pragma unroll
            for (int j = 0; j < 4; j++) {
                float p = __expf(sc[j] - mn);
                Ps[(rowb + i) * PS_STRIDE + colb + j] = p;
                rs += p;
            }
            rs += __shfl_xor_sync(0xffffffffu, rs, 8);
            rs += __shfl_xor_sync(0xffffffffu, rs, 4);
            rs += __shfl_xor_sync(0xffffffffu, rs, 2);
            rs += __shfl_xor_sync(0xffffffffu, rs, 1);
            lsum[i] = lsum[i] * al + rs;
            ull alp = pack2(al, al);
            #pragma unroll
            for (int j = 0; j < 4; j++) o2[i][j] = mul2(o2[i][j], alp);
        }
        __syncthreads();

        const float* Vg = g_V + (size_t)s0 * INNER + h * EDIM;
        #pragma unroll
        for (int i = 0; i < 8; i++) {
            int f  = tid + i * 256;
            int sr = f >> 5;
            int c  = (f & 31) * 4;
            float4 v = make_float4(0.f, 0.f, 0.f, 0.f);
            if (s0 + sr < SD) v = *(const float4*)(Vg + (size_t)sr * INNER + c);
            *(float4*)&KV[sr * 128 + c] = v;
        }
        __syncthreads();

        #pragma unroll 2
        for (int s = 0; s < 64; s++) {
            ull b2[4];
            b2[0] = *(const ull*)&KV[s * 128 + colb2];
            b2[1] = *(const ull*)&KV[s * 128 + colb2 + 2];
            b2[2] = *(const ull*)&KV[s * 128 + colb2 + 4];
            b2[3] = *(const ull*)&KV[s * 128 + colb2 + 6];
            #pragma unroll
            for (int i = 0; i < 4; i++) {
                float a = Ps[(rowb + i) * PS_STRIDE + s];
                ull a2 = pack2(a, a);
                fma2(o2[i][0], a2, b2[0]);
                fma2(o2[i][1], a2, b2[1]);
                fma2(o2[i][2], a2, b2[2]);
                fma2(o2[i][3], a2, b2[3]);
            }
        }
        __syncthreads();
    }

    float* Cg = g_ctx + ((size_t)(b * LD + l0 + rowb)) * INNER + h * EDIM + colb2;
    #pragma unroll
    for (int i = 0; i < 4; i++) {
        float inv = 1.f / lsum[i];
        float2 p0 = unpack2(o2[i][0]), p1 = unpack2(o2[i][1]);
        float2 p2 = unpack2(o2[i][2]), p3 = unpack2(o2[i][3]);
        float4 oA = make_float4(p0.x * inv, p0.y * inv, p1.x * inv, p1.y * inv);
        float4 oB = make_float4(p2.x * inv, p2.y * inv, p3.x * inv, p3.y * inv);
        *(float4*)(Cg + (size_t)i * INNER)     = oA;
        *(float4*)(Cg + (size_t)i * INNER + 4) = oB;
    }
}

// ---- launch ---------------------------------------------------------------
extern "C" void kernel_launch(void* const* d_in, const int* in_sizes, int n_in,
                              void* d_out, int out_size)
{
    (void)in_sizes; (void)n_in; (void)out_size;
    const float* te = (const float*)d_in[0];
    const float* se = (const float*)d_in[1];
    const float* ve = (const float*)d_in[2];
    const float* Wq = (const float*)d_in[3];
    const float* bq = (const float*)d_in[4];
    const float* Wk = (const float*)d_in[5];
    const float* bk = (const float*)d_in[6];
    const float* Wv = (const float*)d_in[7];
    const float* bv = (const float*)d_in[8];
    const float* Wo = (const float*)d_in[9];
    const float* bo = (const float*)d_in[10];
    float* out = (float*)d_out;

    float *Qp, *Kp, *Vp, *Cp;
    cudaGetSymbolAddress((void**)&Qp, g_Q);
    cudaGetSymbolAddress((void**)&Kp, g_K);
    cudaGetSymbolAddress((void**)&Vp, g_V);
    cudaGetSymbolAddress((void**)&Cp, g_ctx);

    cudaFuncSetAttribute(attn_kernel,
                         cudaFuncAttributeMaxDynamicSharedMemorySize, ATTN_SMEM);
    cudaFuncSetAttribute(proj_qkv,
                         cudaFuncAttributeMaxDynamicSharedMemorySize, GEMM_SMEM_BYTES);
    cudaFuncSetAttribute(sgemm3,
                         cudaFuncAttributeMaxDynamicSharedMemorySize, GEMM_SMEM_BYTES);

    dim3 blk(256);
    // 1) Q,K,V projections fused, tensor cores (grid 8 x 80)
    proj_qkv<<<dim3(INNER / 128, 80), blk, GEMM_SMEM_BYTES>>>(
        te, se, ve, Wq, bq, Wk, bk, Wv, bv, Qp, Kp, Vp);
    // 2) attention -> ctx (fp32)
    attn_kernel<<<dim3(LD / 64, NH, BD), blk, ATTN_SMEM>>>();
    // 3) out = ctx @ Wo + bo (8192 x 4096, K=1024), tensor cores
    sgemm3<<<dim3(DLLM / 128, (BD * LD) / 128), blk, GEMM_SMEM_BYTES>>>(
        Cp, Wo, bo, out, BD * LD, DLLM, INNER);
}

// round 13
// speedup vs baseline: 1.1632x; 1.1632x over previous
#include <cuda_runtime.h>
#include <cuda_bf16.h>
#include <math.h>

// Problem constants (fixed by reference setup_inputs)
#define BD     8
#define LD     1024
#define SD     1000
#define DMODEL 1024
#define DLLM   4096
#define NH     8
#define EDIM   128
#define INNER  1024   // NH*EDIM

#define ATTN_SCALE 0.088388347648318447f  // 1/sqrt(128)

typedef unsigned long long ull;
typedef unsigned int u32;

// Scratch (device globals: no allocation allowed)
__device__ float g_Q[(size_t)BD * LD * INNER];    // (B*L, INNER)
__device__ float g_K[(size_t)SD * INNER];         // (S, INNER)
__device__ float g_V[(size_t)SD * INNER];         // (S, INNER)
__device__ float g_ctx[(size_t)BD * LD * INNER];  // (B*L, INNER)

// ---- packed f32x2 helpers (attention kernel) -------------------------------
__device__ __forceinline__ ull pack2(float x, float y) {
    ull r; asm("mov.b64 %0, {%1,%2};" : "=l"(r) : "f"(x), "f"(y)); return r;
}
__device__ __forceinline__ float2 unpack2(ull v) {
    float2 r; asm("mov.b64 {%0,%1}, %2;" : "=f"(r.x), "=f"(r.y) : "l"(v)); return r;
}
__device__ __forceinline__ void fma2(ull& c, ull a, ull b) {
    asm("fma.rn.f32x2 %0, %1, %2, %0;" : "+l"(c) : "l"(a), "l"(b));
}
__device__ __forceinline__ ull mul2(ull a, ull b) {
    ull r; asm("mul.rn.f32x2 %0, %1, %2;" : "=l"(r) : "l"(a), "l"(b)); return r;
}

// ============================================================================
// Split-bf16 3-pass tensor-core GEMM: C = A@W + bias (fp32 in/out).
// a = ah + al (bf16), b = bh + bl; D += ah*bh + ah*bl + al*bh (rel_err ~3.6e-5
// measured). CTA: 128x128 tile, BK=16, 256 threads (8 warps, each 32m x 64n).
// R11 ncu: tensor=31%, issue=25.9%, occ=19.2% -> latency-bound on 48 scalar
// LDS.32 fragment loads per warp-kstep. This version replaces them with 12
// ldmatrix.x4 (LDSM) per warp-kstep; TSTRIDE=24 (48B rows) is conflict-free
// for LDSM (8 rows cover all 32 banks).
// ============================================================================
#define TSTRIDE 24
#define TILE_E  (128 * TSTRIDE)            // 3072 bf16 per array
#define REG_AH  0                          // byte offsets of the 4 arrays
#define REG_AL  (TILE_E * 2)               // 6144
#define REG_BH  (TILE_E * 4)               // 12288
#define REG_BL  (TILE_E * 6)               // 18432
#define BUF_BYTES (TILE_E * 8)             // 24576 per buffer
#define GEMM_SMEM_BYTES (BUF_BYTES * 2)    // 49152

__device__ __forceinline__ void mma_bf16(float* d, const u32* a, u32 b0, u32 b1) {
    asm volatile(
        "mma.sync.aligned.m16n8k16.row.col.f32.bf16.bf16.f32 "
        "{%0,%1,%2,%3}, {%4,%5,%6,%7}, {%8,%9}, {%0,%1,%2,%3};\n"
        : "+f"(d[0]), "+f"(d[1]), "+f"(d[2]), "+f"(d[3])
        : "r"(a[0]), "r"(a[1]), "r"(a[2]), "r"(a[3]), "r"(b0), "r"(b1));
}

__device__ __forceinline__ void ldsm4(u32& r0, u32& r1, u32& r2, u32& r3, u32 addr) {
    asm volatile(
        "ldmatrix.sync.aligned.m8n8.x4.shared.b16 {%0,%1,%2,%3}, [%4];"
        : "=r"(r0), "=r"(r1), "=r"(r2), "=r"(r3) : "r"(addr));
}

// Split 8 consecutive floats into hi/lo bf16 and store as two STS.128.
__device__ __forceinline__ void split8_sts(const float* v,
                                           __nv_bfloat16* Hdst,
                                           __nv_bfloat16* Ldst) {
    u32 h[4], l[4];
    #pragma unroll
    for (int i = 0; i < 4; i++) {
        float x = v[2 * i], y = v[2 * i + 1];
        __nv_bfloat162 hh = __floats2bfloat162_rn(x, y);
        float rx = x - __bfloat162float(hh.x);
        float ry = y - __bfloat162float(hh.y);
        __nv_bfloat162 ll = __floats2bfloat162_rn(rx, ry);
        h[i] = *(u32*)&hh;
        l[i] = *(u32*)&ll;
    }
    *(uint4*)Hdst = make_uint4(h[0], h[1], h[2], h[3]);
    *(uint4*)Ldst = make_uint4(l[0], l[1], l[2], l[3]);
}

__device__ __forceinline__ void gemm3_body(
    const float* __restrict__ A, const float* __restrict__ W,
    const float* __restrict__ bias, float* __restrict__ C,
    int M, int N, int K, int row0, int col0)
{
    extern __shared__ __nv_bfloat16 sb[];
    const u32 sb_u32 = (u32)__cvta_generic_to_shared(sb);

    const int tid  = threadIdx.x;
    const int lane = tid & 31;
    const int warp = tid >> 5;
    const int gid  = lane >> 2;   // 0..7
    const int tig  = lane & 3;    // 0..3
    const int m0   = (warp & 3) * 32;   // warp m origin in tile
    const int n0   = (warp >> 2) * 64;  // warp n origin in tile

    // ldmatrix per-lane source offsets (bytes within one buffer)
    // A (row-major k, 48B rows): matrices (r0-7,k0)(r8-15,k0)(r0-7,k8)(r8-15,k8)
    const int aRow = lane & 15;
    const int aKb  = (lane >> 4) * 16;          // 0 or 16 bytes
    // B (n-major, 48B rows): matrices (n0-7,k0)(n0-7,k8)(n8-15,k0)(n8-15,k8)
    const int bRow = (lane & 7) + ((lane & 16) >> 1);   // 0..15
    const int bKb  = (lane & 8) * 2;            // 0 or 16 bytes
    u32 aoff[2], boff[4];
    #pragma unroll
    for (int mt = 0; mt < 2; mt++)
        aoff[mt] = (u32)((m0 + mt * 16 + aRow) * (TSTRIDE * 2) + aKb);
    #pragma unroll
    for (int jp = 0; jp < 4; jp++)
        boff[jp] = (u32)((n0 + jp * 16 + bRow) * (TSTRIDE * 2) + bKb);

    // loader mapping: 256 threads, lr = row (A) / n (B), lk = k base (0 or 8)
    const int lr = tid & 127;
    const int lk = (tid >> 7) * 8;

    float acc[2][8][4];
    #pragma unroll
    for (int mt = 0; mt < 2; mt++)
        #pragma unroll
        for (int j = 0; j < 8; j++)
            #pragma unroll
            for (int q = 0; q < 4; q++) acc[mt][j][q] = 0.f;

    const bool arow_ok = (row0 + lr) < M;
    const float* Apt = A + (size_t)(row0 + lr) * K + lk;      // A[row][lk+..]
    const float* Wpt = W + (size_t)lk * N + (col0 + lr);      // W[lk+i][col0+lr]

    float av[8];   // A prefetch (8 consecutive k)
    float bv[8];   // B prefetch (8 consecutive k, one n) -- transposed store

    // ---- prefetch tile 0 ----
    {
        float4 t0 = make_float4(0.f, 0.f, 0.f, 0.f), t1 = t0;
        if (arow_ok) { t0 = *(const float4*)(Apt); t1 = *(const float4*)(Apt + 4); }
        av[0]=t0.x; av[1]=t0.y; av[2]=t0.z; av[3]=t0.w;
        av[4]=t1.x; av[5]=t1.y; av[6]=t1.z; av[7]=t1.w;
        #pragma unroll
        for (int i = 0; i < 8; i++) bv[i] = Wpt[(size_t)i * N];
    }
    // ---- store tile 0 into buffer 0 ----
    {
        __nv_bfloat16* Ah = sb;                 __nv_bfloat16* Al = Ah + TILE_E;
        __nv_bfloat16* Bh = Al + TILE_E;        __nv_bfloat16* Bl = Bh + TILE_E;
        split8_sts(av, &Ah[lr * TSTRIDE + lk], &Al[lr * TSTRIDE + lk]);
        split8_sts(bv, &Bh[lr * TSTRIDE + lk], &Bl[lr * TSTRIDE + lk]);
    }
    __syncthreads();

    int cur = 0;
    for (int k0 = 16; k0 <= K; k0 += 16) {
        const bool more = (k0 < K);
        if (more) {
            float4 t0 = make_float4(0.f, 0.f, 0.f, 0.f), t1 = t0;
            if (arow_ok) { t0 = *(const float4*)(Apt + k0); t1 = *(const float4*)(Apt + k0 + 4); }
            av[0]=t0.x; av[1]=t0.y; av[2]=t0.z; av[3]=t0.w;
            av[4]=t1.x; av[5]=t1.y; av[6]=t1.z; av[7]=t1.w;
            #pragma unroll
            for (int i = 0; i < 8; i++) bv[i] = Wpt[(size_t)(k0 + i) * N];
        }

        // ---- compute on current buffer (all fragment loads via ldmatrix) ----
        const u32 buf = sb_u32 + (u32)(cur * BUF_BYTES);

        u32 ah[2][4], al[2][4];
        #pragma unroll
        for (int mt = 0; mt < 2; mt++) {
            ldsm4(ah[mt][0], ah[mt][1], ah[mt][2], ah[mt][3], buf + REG_AH + aoff[mt]);
            ldsm4(al[mt][0], al[mt][1], al[mt][2], al[mt][3], buf + REG_AL + aoff[mt]);
        }
        #pragma unroll
        for (int jp = 0; jp < 4; jp++) {
            u32 bh[4], bl[4];
            ldsm4(bh[0], bh[1], bh[2], bh[3], buf + REG_BH + boff[jp]);
            ldsm4(bl[0], bl[1], bl[2], bl[3], buf + REG_BL + boff[jp]);
            #pragma unroll
            for (int mt = 0; mt < 2; mt++) {
                mma_bf16(acc[mt][2 * jp    ], ah[mt], bh[0], bh[1]);
                mma_bf16(acc[mt][2 * jp    ], ah[mt], bl[0], bl[1]);
                mma_bf16(acc[mt][2 * jp    ], al[mt], bh[0], bh[1]);
                mma_bf16(acc[mt][2 * jp + 1], ah[mt], bh[2], bh[3]);
                mma_bf16(acc[mt][2 * jp + 1], ah[mt], bl[2], bl[3]);
                mma_bf16(acc[mt][2 * jp + 1], al[mt], bh[2], bh[3]);
            }
        }

        if (more) {
            int nxt = cur ^ 1;
            __nv_bfloat16* base = sb + (size_t)nxt * 4 * TILE_E;
            __nv_bfloat16* AhN = base;
            __nv_bfloat16* AlN = AhN + TILE_E;
            __nv_bfloat16* BhN = AlN + TILE_E;
            __nv_bfloat16* BlN = BhN + TILE_E;
            split8_sts(av, &AhN[lr * TSTRIDE + lk], &AlN[lr * TSTRIDE + lk]);
            split8_sts(bv, &BhN[lr * TSTRIDE + lk], &BlN[lr * TSTRIDE + lk]);
            __syncthreads();
            cur = nxt;
        }
    }

    // ---- epilogue: add bias, store fp32 ----
    #pragma unroll
    for (int j = 0; j < 8; j++) {
        int col = col0 + n0 + j * 8 + tig * 2;
        float2 bb = *(const float2*)(bias + col);
        #pragma unroll
        for (int mt = 0; mt < 2; mt++) {
            int r = row0 + m0 + mt * 16 + gid;
            if (r < M) {
                float2 o = make_float2(acc[mt][j][0] + bb.x, acc[mt][j][1] + bb.y);
                *(float2*)(C + (size_t)r * N + col) = o;
            }
            if (r + 8 < M) {
                float2 o = make_float2(acc[mt][j][2] + bb.x, acc[mt][j][3] + bb.y);
                *(float2*)(C + (size_t)(r + 8) * N + col) = o;
            }
        }
    }
}

// Big output projection.
__global__ __launch_bounds__(256, 2) void sgemm3(
    const float* __restrict__ A, const float* __restrict__ W,
    const float* __restrict__ bias, float* __restrict__ C,
    int M, int N, int K)
{
    gemm3_body(A, W, bias, C, M, N, K, blockIdx.y * 128, blockIdx.x * 128);
}

// Fused Q+K+V projection: grid (8, 80), no empty CTAs.
__global__ __launch_bounds__(256, 2) void proj_qkv(
    const float* __restrict__ te,
    const float* __restrict__ se, const float* __restrict__ ve,
    const float* __restrict__ Wq, const float* __restrict__ bq,
    const float* __restrict__ Wk, const float* __restrict__ bk,
    const float* __restrict__ Wv, const float* __restrict__ bv,
    float* __restrict__ Qp, float* __restrict__ Kp, float* __restrict__ Vp)
{
    const int y = blockIdx.y;
    const float *A, *W, *bia;
    float* C;
    int M, K, row0;
    if (y < 64) {
        A = te; W = Wq; bia = bq; C = Qp;
        M = BD * LD; K = DMODEL; row0 = y * 128;
    } else if (y < 72) {
        A = se; W = Wk; bia = bk; C = Kp;
        M = SD; K = DLLM; row0 = (y - 64) * 128;
    } else {
        A = ve; W = Wv; bia = bv; C = Vp;
        M = SD; K = DLLM; row0 = (y - 72) * 128;
    }
    gemm3_body(A, W, bia, C, M, INNER, K, row0, blockIdx.x * 128);
}

// ---- Flash attention (fp32, online softmax) -- unchanged passing version ---
#define AQ_STRIDE 132
#define KT_STRIDE 66
#define PS_STRIDE 66
#define KV_FLOATS 8448  // max(128*KT_STRIDE=8448, 64*128=8192)
#define ATTN_SMEM ((64 * AQ_STRIDE + KV_FLOATS + 64 * PS_STRIDE) * 4)

__global__ __launch_bounds__(256, 2) void attn_kernel()
{
    extern __shared__ float sm[];
    float* Qs = sm;                         // [64][AQ_STRIDE]
    float* KV = sm + 64 * AQ_STRIDE;        // K^T [128][KT_STRIDE] or V [64][128]
    float* Ps = KV + KV_FLOATS;             // [64][PS_STRIDE]

    const int tid = threadIdx.x;
    const int l0  = blockIdx.x * 64;
    const int h   = blockIdx.y;
    const int b   = blockIdx.z;

    const float* Qg = g_Q + ((size_t)(b * LD + l0)) * INNER + h * EDIM;
    #pragma unroll
    for (int i = 0; i < 8; i++) {
        int f = tid + i * 256;
        int r = f >> 5;
        int c = (f & 31) * 4;
        float4 v = *(const float4*)(Qg + (size_t)r * INNER + c);
        Qs[r * AQ_STRIDE + c + 0] = v.x;
        Qs[r * AQ_STRIDE + c + 1] = v.y;
        Qs[r * AQ_STRIDE + c + 2] = v.z;
        Qs[r * AQ_STRIDE + c + 3] = v.w;
    }

    const int rowb  = (tid >> 4) * 4;
    const int colb  = (tid & 15) * 4;
    const int colb2 = (tid & 15) * 8;

    float m[4], lsum[4];
    ull o2[4][4];
    #pragma unroll
    for (int i = 0; i < 4; i++) {
        m[i] = -INFINITY;
        lsum[i] = 0.f;
        #pragma unroll
        for (int j = 0; j < 4; j++) o2[i][j] = 0ull;
    }
    __syncthreads();

    for (int s0 = 0; s0 < SD; s0 += 64) {
        const float* Kg = g_K + (size_t)s0 * INNER + h * EDIM;
        #pragma unroll
        for (int i = 0; i < 8; i++) {
            int f  = tid + i * 256;
            int sr = f >> 5;
            int c  = (f & 31) * 4;
            float4 v = make_float4(0.f, 0.f, 0.f, 0.f);
            if (s0 + sr < SD) v = *(const float4*)(Kg + (size_t)sr * INNER + c);
            KV[(c + 0) * KT_STRIDE + sr] = v.x;
            KV[(c + 1) * KT_STRIDE + sr] = v.y;
            KV[(c + 2) * KT_STRIDE + sr] = v.z;
            KV[(c + 3) * KT_STRIDE + sr] = v.w;
        }
        __syncthreads();

        ull pc2[4][2];
        #pragma unroll
        for (int i = 0; i < 4; i++) { pc2[i][0] = 0ull; pc2[i][1] = 0ull; }
        #pragma unroll 4
        for (int e = 0; e < EDIM; e++) {
            ull b0 = *(const ull*)&KV[e * KT_STRIDE + colb];
            ull b1 = *(const ull*)&KV[e * KT_STRIDE + colb + 2];
            #pragma unroll
            for (int i = 0; i < 4; i++) {
                float a = Qs[(rowb + i) * AQ_STRIDE + e];
                ull a2 = pack2(a, a);
                fma2(pc2[i][0], a2, b0);
                fma2(pc2[i][1], a2, b1);
            }
        }

        #pragma unroll
        for (int i = 0; i < 4; i++) {
            float2 q0 = unpack2(pc2[i][0]);
            float2 q1 = unpack2(pc2[i][1]);
            float sc[4] = {q0.x, q0.y, q1.x, q1.y};
            #pragma unroll
            for (int j = 0; j < 4; j++) {
                sc[j] *= ATTN_SCALE;
                if (s0 + colb + j >= SD) sc[j] = -INFINITY;
            }
            float mx = fmaxf(fmaxf(sc[0], sc[1]), fmaxf(sc[2], sc[3]));
            mx = fmaxf(mx, __shfl_xor_sync(0xffffffffu, mx, 8));
            mx = fmaxf(mx, __shfl_xor_sync(0xffffffffu, mx, 4));
            mx = fmaxf(mx, __shfl_xor_sync(0xffffffffu, mx, 2));
            mx = fmaxf(mx, __shfl_xor_sync(0xffffffffu, mx, 1));
            float mn = fmaxf(m[i], mx);
            float al = __expf(m[i] - mn);
            m[i] = mn;
            float rs = 0.f;
            #pragma unroll
            for (int j = 0; j < 4; j++) {
                float p = __expf(sc[j] - mn);
                Ps[(rowb + i) * PS_STRIDE + colb + j] = p;
                rs += p;
            }
            rs += __shfl_xor_sync(0xffffffffu, rs, 8);
            rs += __shfl_xor_sync(0xffffffffu, rs, 4);
            rs += __shfl_xor_sync(0xffffffffu, rs, 2);
            rs += __shfl_xor_sync(0xffffffffu, rs, 1);
            lsum[i] = lsum[i] * al + rs;
            ull alp = pack2(al, al);
            #pragma unroll
            for (int j = 0; j < 4; j++) o2[i][j] = mul2(o2[i][j], alp);
        }
        __syncthreads();

        const float* Vg = g_V + (size_t)s0 * INNER + h * EDIM;
        #pragma unroll
        for (int i = 0; i < 8; i++) {
            int f  = tid + i * 256;
            int sr = f >> 5;
            int c  = (f & 31) * 4;
            float4 v = make_float4(0.f, 0.f, 0.f, 0.f);
            if (s0 + sr < SD) v = *(const float4*)(Vg + (size_t)sr * INNER + c);
            *(float4*)&KV[sr * 128 + c] = v;
        }
        __syncthreads();

        #pragma unroll 2
        for (int s = 0; s < 64; s++) {
            ull b2[4];
            b2[0] = *(const ull*)&KV[s * 128 + colb2];
            b2[1] = *(const ull*)&KV[s * 128 + colb2 + 2];
            b2[2] = *(const ull*)&KV[s * 128 + colb2 + 4];
            b2[3] = *(const ull*)&KV[s * 128 + colb2 + 6];
            #pragma unroll
            for (int i = 0; i < 4; i++) {
                float a = Ps[(rowb + i) * PS_STRIDE + s];
                ull a2 = pack2(a, a);
                fma2(o2[i][0], a2, b2[0]);
                fma2(o2[i][1], a2, b2[1]);
                fma2(o2[i][2], a2, b2[2]);
                fma2(o2[i][3], a2, b2[3]);
            }
        }
        __syncthreads();
    }

    float* Cg = g_ctx + ((size_t)(b * LD + l0 + rowb)) * INNER + h * EDIM + colb2;
    #pragma unroll
    for (int i = 0; i < 4; i++) {
        float inv = 1.f / lsum[i];
        float2 p0 = unpack2(o2[i][0]), p1 = unpack2(o2[i][1]);
        float2 p2 = unpack2(o2[i][2]), p3 = unpack2(o2[i][3]);
        float4 oA = make_float4(p0.x * inv, p0.y * inv, p1.x * inv, p1.y * inv);
        float4 oB = make_float4(p2.x * inv, p2.y * inv, p3.x * inv, p3.y * inv);
        *(float4*)(Cg + (size_t)i * INNER)     = oA;
        *(float4*)(Cg + (size_t)i * INNER + 4) = oB;
    }
}

// ---- launch ---------------------------------------------------------------
extern "C" void kernel_launch(void* const* d_in, const int* in_sizes, int n_in,
                              void* d_out, int out_size)
{
    (void)in_sizes; (void)n_in; (void)out_size;
    const float* te = (const float*)d_in[0];
    const float* se = (const float*)d_in[1];
    const float* ve = (const float*)d_in[2];
    const float* Wq = (const float*)d_in[3];
    const float* bq = (const float*)d_in[4];
    const float* Wk = (const float*)d_in[5];
    const float* bk = (const float*)d_in[6];
    const float* Wv = (const float*)d_in[7];
    const float* bv = (const float*)d_in[8];
    const float* Wo = (const float*)d_in[9];
    const float* bo = (const float*)d_in[10];
    float* out = (float*)d_out;

    float *Qp, *Kp, *Vp, *Cp;
    cudaGetSymbolAddress((void**)&Qp, g_Q);
    cudaGetSymbolAddress((void**)&Kp, g_K);
    cudaGetSymbolAddress((void**)&Vp, g_V);
    cudaGetSymbolAddress((void**)&Cp, g_ctx);

    cudaFuncSetAttribute(attn_kernel,
                         cudaFuncAttributeMaxDynamicSharedMemorySize, ATTN_SMEM);
    cudaFuncSetAttribute(proj_qkv,
                         cudaFuncAttributeMaxDynamicSharedMemorySize, GEMM_SMEM_BYTES);
    cudaFuncSetAttribute(sgemm3,
                         cudaFuncAttributeMaxDynamicSharedMemorySize, GEMM_SMEM_BYTES);

    dim3 blk(256);
    // 1) Q,K,V projections fused, tensor cores (grid 8 x 80)
    proj_qkv<<<dim3(INNER / 128, 80), blk, GEMM_SMEM_BYTES>>>(
        te, se, ve, Wq, bq, Wk, bk, Wv, bv, Qp, Kp, Vp);
    // 2) attention -> ctx (fp32)
    attn_kernel<<<dim3(LD / 64, NH, BD), blk, ATTN_SMEM>>>();
    // 3) out = ctx @ Wo + bo (8192 x 4096, K=1024), tensor cores
    sgemm3<<<dim3(DLLM / 128, (BD * LD) / 128), blk, GEMM_SMEM_BYTES>>>(
        Cp, Wo, bo, out, BD * LD, DLLM, INNER);
}